// round 2
// baseline (speedup 1.0000x reference)
#include <cuda_runtime.h>
#include <math.h>

// Problem constants
#define NB   32          // batch
#define HH   192         // H == W
#define CC   64          // channels
#define SBD  64          // 3x3 sub-blocks per spatial dim (192/3)
#define EPS  1e-5f
#define PADT 33          // padded token-pair stride (bank-conflict pad)

// Scratch (device globals — allocation-free)
__device__ __align__(16) float g_S[NB * SBD * SBD * CC];       // 33.5 MB sub-block sums [b][sh][sw][c]
__device__ __align__(16) float g_tok[2 * NB * 32 * 32 * CC];   // 16.8 MB tokens [p][b][i][j][c]

typedef unsigned long long u64;

__device__ __forceinline__ float gelu_exact(float v) {
    return 0.5f * v * (1.0f + erff(v * 0.7071067811865476f));
}
__device__ __forceinline__ u64 pk2(float lo, float hi) {
    u64 r; asm("mov.b64 %0, {%1, %2};" : "=l"(r) : "f"(lo), "f"(hi)); return r;
}
__device__ __forceinline__ void upk2(float& lo, float& hi, u64 v) {
    asm("mov.b64 {%0, %1}, %2;" : "=f"(lo), "=f"(hi) : "l"(v));
}
__device__ __forceinline__ u64 ffma2(u64 a, u64 b, u64 c) {
    u64 d; asm("fma.rn.f32x2 %0, %1, %2, %3;" : "=l"(d) : "l"(a), "l"(b), "l"(c)); return d;
}

// ---------------------------------------------------------------------------
// K1: 3x3 sub-block sums. One thread per (b, sh, sw, c4) using float4 loads.
// ---------------------------------------------------------------------------
__global__ void __launch_bounds__(256) k1_subsum(const float* __restrict__ x) {
    int tid = blockIdx.x * blockDim.x + threadIdx.x;   // 2,097,152 threads exactly
    int c4 = tid & 15;
    int sw = (tid >> 4) & 63;
    int sh = (tid >> 10) & 63;
    int b  = tid >> 16;
    const float4* x4 = (const float4*)x;
    float4 acc = make_float4(0.f, 0.f, 0.f, 0.f);
    int rowbase = (b * HH + sh * 3) * HH + sw * 3;
#pragma unroll
    for (int dh = 0; dh < 3; dh++)
#pragma unroll
        for (int dw = 0; dw < 3; dw++) {
            float4 v = x4[(rowbase + dh * HH + dw) * 16 + c4];
            acc.x += v.x; acc.y += v.y; acc.z += v.z; acc.w += v.w;
        }
    ((float4*)g_S)[tid] = acc;
}

// ---------------------------------------------------------------------------
// Shared GEMM(64x64) + LayerNorm + GELU for a 32-row tile.
// Thread layout: ctx = tid&15 owns channels [4*ctx, 4*ctx+4); cty = tid>>4
// owns tokens {2*cty, 2*cty+1}. Channel pairs packed into f32x2 FMAs.
// xs holds duplicated pairs (x,x) per [k][token].
// ---------------------------------------------------------------------------
__device__ __forceinline__ void gemm_ln_gelu(
    const float* Ws, const float2* xs,
    const float* __restrict__ bias, const float* __restrict__ gam,
    const float* __restrict__ bet,
    int ctx, int cty, float y[2][4])
{
    int c0 = ctx * 4;
    float2 b01 = *(const float2*)(bias + c0);
    float2 b23 = *(const float2*)(bias + c0 + 2);
    u64 acc00 = pk2(b01.x, b01.y), acc01 = pk2(b23.x, b23.y);
    u64 acc10 = acc00, acc11 = acc01;
#pragma unroll 8
    for (int k = 0; k < 64; k++) {
        u64 w0 = *(const u64*)(Ws + k * 64 + c0);
        u64 w1 = *(const u64*)(Ws + k * 64 + c0 + 2);
        u64 x0 = *(const u64*)(xs + k * PADT + cty * 2);
        u64 x1 = *(const u64*)(xs + k * PADT + cty * 2 + 1);
        acc00 = ffma2(x0, w0, acc00);
        acc01 = ffma2(x0, w1, acc01);
        acc10 = ffma2(x1, w0, acc10);
        acc11 = ffma2(x1, w1, acc11);
    }
    upk2(y[0][0], y[0][1], acc00); upk2(y[0][2], y[0][3], acc01);
    upk2(y[1][0], y[1][1], acc10); upk2(y[1][2], y[1][3], acc11);
#pragma unroll
    for (int t = 0; t < 2; t++) {
        float s = y[t][0] + y[t][1] + y[t][2] + y[t][3];
#pragma unroll
        for (int m = 1; m < 16; m <<= 1) s += __shfl_xor_sync(0xffffffffu, s, m);
        float mean = s * (1.0f / 64.0f);
        float v = 0.f;
#pragma unroll
        for (int j = 0; j < 4; j++) { float d = y[t][j] - mean; v += d * d; }
#pragma unroll
        for (int m = 1; m < 16; m <<= 1) v += __shfl_xor_sync(0xffffffffu, v, m);
        float rstd = rsqrtf(v * (1.0f / 64.0f) + EPS);
#pragma unroll
        for (int j = 0; j < 4; j++) {
            float yn = (y[t][j] - mean) * rstd * __ldg(gam + c0 + j) + __ldg(bet + c0 + j);
            y[t][j] = gelu_exact(yn);
        }
    }
}

// ---------------------------------------------------------------------------
// K2: token projection for both paths (p=0 regular, p=1 shifted).
// 65,536 token rows, 32 per CTA. x = (sum of 4 sub-block sums)/36.
// ---------------------------------------------------------------------------
__global__ void __launch_bounds__(256) k2_token(
    const float* __restrict__ tW, const float* __restrict__ tb,
    const float* __restrict__ tg, const float* __restrict__ tbe)
{
    __shared__ float  Ws[4096];
    __shared__ float2 xs[64 * PADT];
    int tid = threadIdx.x;
    for (int i = tid; i < 4096; i += 256) Ws[i] = tW[i];
    int R0 = blockIdx.x * 32;
#pragma unroll
    for (int e = 0; e < 8; e++) {
        int idx = e * 256 + tid;
        int t = idx >> 6, c = idx & 63;
        int R = R0 + t;
        int p = R >> 15, rem = R & 32767;
        int bb = rem >> 10, ii = (rem >> 5) & 31, jj = rem & 31;
        int r0, r1, q0, q1;
        if (p == 0) { r0 = 2 * ii;            r1 = 2 * ii + 1;
                      q0 = 2 * jj;            q1 = 2 * jj + 1; }
        else        { r0 = (2 * ii + 1) & 63; r1 = (2 * ii + 2) & 63;
                      q0 = (2 * jj + 1) & 63; q1 = (2 * jj + 2) & 63; }
        const float* Sb = g_S + bb * (SBD * SBD * CC);
        float s = Sb[(r0 * 64 + q0) * 64 + c] + Sb[(r0 * 64 + q1) * 64 + c]
                + Sb[(r1 * 64 + q0) * 64 + c] + Sb[(r1 * 64 + q1) * 64 + c];
        float xv = s * (1.0f / 36.0f);
        xs[c * PADT + t] = make_float2(xv, xv);
    }
    __syncthreads();
    int ctx = tid & 15, cty = tid >> 4;
    float y[2][4];
    gemm_ln_gelu(Ws, xs, tb, tg, tbe, ctx, cty, y);
#pragma unroll
    for (int t = 0; t < 2; t++) {
        int R = R0 + cty * 2 + t;
        ((float4*)g_tok)[R * 16 + ctx] = make_float4(y[t][0], y[t][1], y[t][2], y[t][3]);
    }
}

// ---------------------------------------------------------------------------
// K3: per unique 3x3 block: x = tokR + tokS; fuse block; out block;
// broadcast to the 9 output pixels. 131,072 rows, 32 per CTA.
// ---------------------------------------------------------------------------
__global__ void __launch_bounds__(256) k3_fuse_out(
    const float* __restrict__ fW, const float* __restrict__ fb,
    const float* __restrict__ fg, const float* __restrict__ fbe,
    const float* __restrict__ oW, const float* __restrict__ ob,
    const float* __restrict__ og, const float* __restrict__ obe,
    float* __restrict__ out)
{
    __shared__ float  Ws[4096];
    __shared__ float2 xs[64 * PADT];
    int tid = threadIdx.x;
    for (int i = tid; i < 4096; i += 256) Ws[i] = fW[i];
    int R0 = blockIdx.x * 32;
#pragma unroll
    for (int e = 0; e < 8; e++) {
        int idx = e * 256 + tid;
        int t = idx >> 6, c = idx & 63;
        int R = R0 + t;
        int bb = R >> 12, qh = (R >> 6) & 63, qw = R & 63;
        int ih = qh >> 1, iw = qw >> 1;
        int sh = ((qh + 63) & 63) >> 1, sw = ((qw + 63) & 63) >> 1;
        float xv = g_tok[((bb * 32 + ih) * 32 + iw) * 64 + c]
                 + g_tok[2097152 + ((bb * 32 + sh) * 32 + sw) * 64 + c];
        xs[c * PADT + t] = make_float2(xv, xv);
    }
    __syncthreads();
    int ctx = tid & 15, cty = tid >> 4;
    float y[2][4];
    gemm_ln_gelu(Ws, xs, fb, fg, fbe, ctx, cty, y);     // fuse block
    __syncthreads();                                     // all reads of xs done
    // feed layer-1 activations back into xs (duplicated pairs); swap W to out_W
#pragma unroll
    for (int t = 0; t < 2; t++)
#pragma unroll
        for (int j = 0; j < 4; j++)
            xs[(ctx * 4 + j) * PADT + cty * 2 + t] = make_float2(y[t][j], y[t][j]);
    for (int i = tid; i < 4096; i += 256) Ws[i] = oW[i];
    __syncthreads();
    gemm_ln_gelu(Ws, xs, ob, og, obe, ctx, cty, y);     // out block
    // broadcast each unique row to its 3x3 pixel block (float4 stores)
#pragma unroll
    for (int t = 0; t < 2; t++) {
        int R = R0 + cty * 2 + t;
        int bb = R >> 12, qh = (R >> 6) & 63, qw = R & 63;
        float4 v = make_float4(y[t][0], y[t][1], y[t][2], y[t][3]);
        float4* o4 = (float4*)out;
        int base = (bb * 36864 + qh * 3 * HH + qw * 3) * 16 + ctx;
#pragma unroll
        for (int dh = 0; dh < 3; dh++)
#pragma unroll
            for (int dw = 0; dw < 3; dw++)
                o4[base + (dh * HH + dw) * 16] = v;
    }
}

// ---------------------------------------------------------------------------
extern "C" void kernel_launch(void* const* d_in, const int* in_sizes, int n_in,
                              void* d_out, int out_size) {
    const float* h_pixel = (const float*)d_in[0];
    const float* tW  = (const float*)d_in[1];
    const float* tb  = (const float*)d_in[2];
    const float* tg  = (const float*)d_in[3];
    const float* tbe = (const float*)d_in[4];
    const float* fW  = (const float*)d_in[5];
    const float* fb  = (const float*)d_in[6];
    const float* fg  = (const float*)d_in[7];
    const float* fbe = (const float*)d_in[8];
    const float* oW  = (const float*)d_in[9];
    const float* ob  = (const float*)d_in[10];
    const float* og  = (const float*)d_in[11];
    const float* obe = (const float*)d_in[12];
    float* out = (float*)d_out;

    k1_subsum<<<8192, 256>>>(h_pixel);
    k2_token<<<2048, 256>>>(tW, tb, tg, tbe);
    k3_fuse_out<<<4096, 256>>>(fW, fb, fg, fbe, oW, ob, og, obe, out);
}

// round 4
// speedup vs baseline: 1.6005x; 1.6005x over previous
#include <cuda_runtime.h>
#include <math.h>

// Problem constants
#define NB    32
#define HH    192
#define CC    64
#define EPS   1e-5f
#define PADXF 132      // floats per k-row of xs (128 tokens + pad, multiple of 4)

// Scratch (device globals — allocation-free)
__device__ __align__(16) float g_S[NB * 64 * 64 * CC];       // 3x3 sub-block sums
__device__ __align__(16) float g_tok[2 * NB * 32 * 32 * CC]; // tokens [p][b][i][j][c]

typedef unsigned long long u64;

__device__ __forceinline__ float gelu_exact(float v) {
    return 0.5f * v * (1.0f + erff(v * 0.7071067811865476f));
}
__device__ __forceinline__ u64 pk2(float lo, float hi) {
    u64 r; asm("mov.b64 %0, {%1, %2};" : "=l"(r) : "f"(lo), "f"(hi)); return r;
}
__device__ __forceinline__ void upk2(float& lo, float& hi, u64 v) {
    asm("mov.b64 {%0, %1}, %2;" : "=f"(lo), "=f"(hi) : "l"(v));
}
__device__ __forceinline__ u64 ffma2(u64 a, u64 b, u64 c) {
    u64 d; asm("fma.rn.f32x2 %0, %1, %2, %3;" : "=l"(d) : "l"(a), "l"(b), "l"(c)); return d;
}

// ---------------------------------------------------------------------------
// K1: 3x3 sub-block sums (unchanged — 82% of DRAM roofline).
// ---------------------------------------------------------------------------
__global__ void __launch_bounds__(256) k1_subsum(const float* __restrict__ x) {
    int tid = blockIdx.x * blockDim.x + threadIdx.x;
    int c4 = tid & 15;
    int sw = (tid >> 4) & 63;
    int sh = (tid >> 10) & 63;
    int b  = tid >> 16;
    const float4* x4 = (const float4*)x;
    float4 acc = make_float4(0.f, 0.f, 0.f, 0.f);
    int rowbase = (b * HH + sh * 3) * HH + sw * 3;
#pragma unroll
    for (int dh = 0; dh < 3; dh++)
#pragma unroll
        for (int dw = 0; dw < 3; dw++) {
            float4 v = x4[(rowbase + dh * HH + dw) * 16 + c4];
            acc.x += v.x; acc.y += v.y; acc.z += v.z; acc.w += v.w;
        }
    ((float4*)g_S)[tid] = acc;
}

// ---------------------------------------------------------------------------
// GEMM(128x64 @ 64x64) + LayerNorm + GELU.
// 256 threads: ctx = tid&7 owns channels {4ctx..4ctx+3, 4ctx+32..4ctx+35};
// cty = tid>>3 owns tokens {4cty..4cty+3}. 32 accumulators as 16 f32x2 pairs.
// Per k: 2 conflict-free LDS.128 (weights), 1 LDS.128 (4 tokens), 4 mov.b64,
// 16 fma.rn.f32x2.
// ---------------------------------------------------------------------------
__device__ __forceinline__ void gemm_ln_gelu(
    const float* Ws, const float* xs,
    const float* __restrict__ bias, const float* __restrict__ gam,
    const float* __restrict__ bet,
    int ctx, int cty, float y[4][8])
{
    int c0 = ctx * 4;
    float2 bl0 = *(const float2*)(bias + c0);
    float2 bl1 = *(const float2*)(bias + c0 + 2);
    float2 bh0 = *(const float2*)(bias + c0 + 32);
    float2 bh1 = *(const float2*)(bias + c0 + 34);
    u64 i0 = pk2(bl0.x, bl0.y), i1 = pk2(bl1.x, bl1.y);
    u64 i2 = pk2(bh0.x, bh0.y), i3 = pk2(bh1.x, bh1.y);
    u64 acc[4][4];
#pragma unroll
    for (int t = 0; t < 4; t++) { acc[t][0] = i0; acc[t][1] = i1; acc[t][2] = i2; acc[t][3] = i3; }
    const float* xrow = xs + cty * 4;
#pragma unroll 4
    for (int k = 0; k < 64; k++) {
        ulonglong2 wl = *(const ulonglong2*)(Ws + k * 64 + c0);
        ulonglong2 wh = *(const ulonglong2*)(Ws + k * 64 + c0 + 32);
        float4 xv = *(const float4*)(xrow + k * PADXF);
        u64 x0 = pk2(xv.x, xv.x), x1 = pk2(xv.y, xv.y);
        u64 x2 = pk2(xv.z, xv.z), x3 = pk2(xv.w, xv.w);
        acc[0][0] = ffma2(x0, wl.x, acc[0][0]); acc[0][1] = ffma2(x0, wl.y, acc[0][1]);
        acc[0][2] = ffma2(x0, wh.x, acc[0][2]); acc[0][3] = ffma2(x0, wh.y, acc[0][3]);
        acc[1][0] = ffma2(x1, wl.x, acc[1][0]); acc[1][1] = ffma2(x1, wl.y, acc[1][1]);
        acc[1][2] = ffma2(x1, wh.x, acc[1][2]); acc[1][3] = ffma2(x1, wh.y, acc[1][3]);
        acc[2][0] = ffma2(x2, wl.x, acc[2][0]); acc[2][1] = ffma2(x2, wl.y, acc[2][1]);
        acc[2][2] = ffma2(x2, wh.x, acc[2][2]); acc[2][3] = ffma2(x2, wh.y, acc[2][3]);
        acc[3][0] = ffma2(x3, wl.x, acc[3][0]); acc[3][1] = ffma2(x3, wl.y, acc[3][1]);
        acc[3][2] = ffma2(x3, wh.x, acc[3][2]); acc[3][3] = ffma2(x3, wh.y, acc[3][3]);
    }
    float4 gl = *(const float4*)(gam + c0);
    float4 gh = *(const float4*)(gam + c0 + 32);
    float4 el = *(const float4*)(bet + c0);
    float4 eh = *(const float4*)(bet + c0 + 32);
    float ga[8] = {gl.x, gl.y, gl.z, gl.w, gh.x, gh.y, gh.z, gh.w};
    float be[8] = {el.x, el.y, el.z, el.w, eh.x, eh.y, eh.z, eh.w};
#pragma unroll
    for (int t = 0; t < 4; t++) {
        float v[8];
        upk2(v[0], v[1], acc[t][0]); upk2(v[2], v[3], acc[t][1]);
        upk2(v[4], v[5], acc[t][2]); upk2(v[6], v[7], acc[t][3]);
        float s = 0.f;
#pragma unroll
        for (int j = 0; j < 8; j++) s += v[j];
        s += __shfl_xor_sync(0xffffffffu, s, 1);
        s += __shfl_xor_sync(0xffffffffu, s, 2);
        s += __shfl_xor_sync(0xffffffffu, s, 4);
        float mean = s * (1.0f / 64.0f);
        float var = 0.f;
#pragma unroll
        for (int j = 0; j < 8; j++) { float d = v[j] - mean; var += d * d; }
        var += __shfl_xor_sync(0xffffffffu, var, 1);
        var += __shfl_xor_sync(0xffffffffu, var, 2);
        var += __shfl_xor_sync(0xffffffffu, var, 4);
        float rstd = rsqrtf(var * (1.0f / 64.0f) + EPS);
#pragma unroll
        for (int j = 0; j < 8; j++) {
            float yn = (v[j] - mean) * rstd * ga[j] + be[j];
            y[t][j] = gelu_exact(yn);
        }
    }
}

// ---------------------------------------------------------------------------
// K2: token projection, both paths. 128 token rows per CTA (512 CTAs).
// ---------------------------------------------------------------------------
__global__ void __launch_bounds__(256) k2_token(
    const float* __restrict__ tW, const float* __restrict__ tb,
    const float* __restrict__ tg, const float* __restrict__ tbe)
{
    extern __shared__ float sm[];
    float* Ws = sm;
    float* xs = sm + 4096;
    int tid = threadIdx.x;
    for (int i = tid; i < 4096; i += 256) Ws[i] = tW[i];
    int R0 = blockIdx.x * 128;
#pragma unroll 4
    for (int e = 0; e < 32; e++) {
        int idx = e * 256 + tid;
        int t = idx >> 6, c = idx & 63;
        int R = R0 + t;
        int p = R >> 15, rem = R & 32767;
        int bb = rem >> 10, ii = (rem >> 5) & 31, jj = rem & 31;
        int r0, r1, q0, q1;
        if (p == 0) { r0 = 2 * ii;            r1 = 2 * ii + 1;
                      q0 = 2 * jj;            q1 = 2 * jj + 1; }
        else        { r0 = (2 * ii + 1) & 63; r1 = (2 * ii + 2) & 63;
                      q0 = (2 * jj + 1) & 63; q1 = (2 * jj + 2) & 63; }
        const float* Sb = g_S + bb * (64 * 64 * CC);
        float s = Sb[(r0 * 64 + q0) * 64 + c] + Sb[(r0 * 64 + q1) * 64 + c]
                + Sb[(r1 * 64 + q0) * 64 + c] + Sb[(r1 * 64 + q1) * 64 + c];
        xs[c * PADXF + t] = s * (1.0f / 36.0f);
    }
    __syncthreads();
    int ctx = tid & 7, cty = tid >> 3;
    float y[4][8];
    gemm_ln_gelu(Ws, xs, tb, tg, tbe, ctx, cty, y);
#pragma unroll
    for (int t = 0; t < 4; t++) {
        int R = R0 + cty * 4 + t;
        ((float4*)g_tok)[R * 16 + ctx]     = make_float4(y[t][0], y[t][1], y[t][2], y[t][3]);
        ((float4*)g_tok)[R * 16 + ctx + 8] = make_float4(y[t][4], y[t][5], y[t][6], y[t][7]);
    }
}

// ---------------------------------------------------------------------------
// K3: fuse block + out block per unique 3x3 block, broadcast to 9 pixels.
// 128 rows per CTA (1024 CTAs).
// ---------------------------------------------------------------------------
__global__ void __launch_bounds__(256) k3_fuse_out(
    const float* __restrict__ fW, const float* __restrict__ fb,
    const float* __restrict__ fg, const float* __restrict__ fbe,
    const float* __restrict__ oW, const float* __restrict__ ob,
    const float* __restrict__ og, const float* __restrict__ obe,
    float* __restrict__ out)
{
    extern __shared__ float sm[];
    float* Ws = sm;
    float* xs = sm + 4096;
    int tid = threadIdx.x;
    for (int i = tid; i < 4096; i += 256) Ws[i] = fW[i];
    int R0 = blockIdx.x * 128;
#pragma unroll 4
    for (int e = 0; e < 32; e++) {
        int idx = e * 256 + tid;
        int t = idx >> 6, c = idx & 63;
        int R = R0 + t;
        int bb = R >> 12, qh = (R >> 6) & 63, qw = R & 63;
        int ih = qh >> 1, iw = qw >> 1;
        int sh = ((qh + 63) & 63) >> 1, sw = ((qw + 63) & 63) >> 1;
        float xv = g_tok[((bb * 32 + ih) * 32 + iw) * 64 + c]
                 + g_tok[2097152 + ((bb * 32 + sh) * 32 + sw) * 64 + c];
        xs[c * PADXF + t] = xv;
    }
    __syncthreads();
    int ctx = tid & 7, cty = tid >> 3;
    float y[4][8];
    gemm_ln_gelu(Ws, xs, fb, fg, fbe, ctx, cty, y);      // fuse block
    __syncthreads();                                      // all xs/Ws reads done
    // write layer-1 activations back; swap weights to out_W
#pragma unroll
    for (int t = 0; t < 4; t++)
#pragma unroll
        for (int j = 0; j < 8; j++) {
            int c = ctx * 4 + (j < 4 ? j : 28 + j);
            xs[c * PADXF + cty * 4 + t] = y[t][j];
        }
    for (int i = tid; i < 4096; i += 256) Ws[i] = oW[i];
    __syncthreads();
    gemm_ln_gelu(Ws, xs, ob, og, obe, ctx, cty, y);      // out block
    // broadcast each unique row to its 3x3 pixel block
    float4* o4 = (float4*)out;
#pragma unroll
    for (int t = 0; t < 4; t++) {
        int R = R0 + cty * 4 + t;
        int bb = R >> 12, qh = (R >> 6) & 63, qw = R & 63;
        float4 vlo = make_float4(y[t][0], y[t][1], y[t][2], y[t][3]);
        float4 vhi = make_float4(y[t][4], y[t][5], y[t][6], y[t][7]);
        int base = (bb * 36864 + qh * 3 * HH + qw * 3) * 16;
#pragma unroll
        for (int dh = 0; dh < 3; dh++)
#pragma unroll
            for (int dw = 0; dw < 3; dw++) {
                int pix = base + (dh * HH + dw) * 16;
                o4[pix + ctx]     = vlo;
                o4[pix + ctx + 8] = vhi;
            }
    }
}

// ---------------------------------------------------------------------------
extern "C" void kernel_launch(void* const* d_in, const int* in_sizes, int n_in,
                              void* d_out, int out_size) {
    const float* h_pixel = (const float*)d_in[0];
    const float* tW  = (const float*)d_in[1];
    const float* tb  = (const float*)d_in[2];
    const float* tg  = (const float*)d_in[3];
    const float* tbe = (const float*)d_in[4];
    const float* fW  = (const float*)d_in[5];
    const float* fb  = (const float*)d_in[6];
    const float* fg  = (const float*)d_in[7];
    const float* fbe = (const float*)d_in[8];
    const float* oW  = (const float*)d_in[9];
    const float* ob  = (const float*)d_in[10];
    const float* og  = (const float*)d_in[11];
    const float* obe = (const float*)d_in[12];
    float* out = (float*)d_out;

    const int SMEMB = (4096 + 64 * PADXF) * (int)sizeof(float);   // 50176 B
    cudaFuncSetAttribute(k2_token,    cudaFuncAttributeMaxDynamicSharedMemorySize, SMEMB);
    cudaFuncSetAttribute(k3_fuse_out, cudaFuncAttributeMaxDynamicSharedMemorySize, SMEMB);

    k1_subsum<<<8192, 256>>>(h_pixel);
    k2_token<<<512, 256, SMEMB>>>(tW, tb, tg, tbe);
    k3_fuse_out<<<1024, 256, SMEMB>>>(fW, fb, fg, fbe, oW, ob, og, obe, out);
}